// round 3
// baseline (speedup 1.0000x reference)
#include <cuda_runtime.h>
#include <cstdint>

#define NN      256
#define EE      65536
#define MMOT    65536
#define NNZ     524288
#define EENNZ   524288
#define SLOPE   0.01f

// ---------------- device scratch (static, no allocations) ----------------
__device__ int   g_is64;
__device__ float g_small[7 * 65536];   // A, x, y, G, y2, T1(L scratch), T
#define OFF_A   0
#define OFF_X   (1 * 65536)
#define OFF_Y   (2 * 65536)
#define OFF_G   (3 * 65536)
#define OFF_Y2  (4 * 65536)
#define OFF_T1  (5 * 65536)
#define OFF_T   (6 * 65536)
__device__ float g_Wc[256 * 64];
__device__ float g_b2[256];
__device__ float g_bc[64];
__device__ float g_dinv[256];
__device__ float g_dis[EE];
__device__ int   g_cnt_he[EE];
__device__ int   g_cnt_col[EE];
__device__ int   g_off_he[EE + 1];
__device__ int   g_off_col[EE + 1];
__device__ int   g_cur_he[EE];
__device__ int   g_cur_col[EE];
__device__ int   g_dnode[NN];
__device__ int   g_members[NNZ];
__device__ int   g_rows[EENNZ];
__device__ float g_w[(size_t)EE * 256];   // dis[e] * mean-agg rows (64 MB)
__device__ float g_v[(size_t)EE * 256];   // GCN+lin2 output per hyperedge (64 MB)

__device__ __forceinline__ int ldidx(const void* p, long long i, int is64) {
    return is64 ? (int)((const long long*)p)[i] : ((const int*)p)[i];
}
__device__ __forceinline__ float lrelu(float x) { return x >= 0.0f ? x : SLOPE * x; }

// ---------------- init + index dtype detection (fused) ----------------
__global__ void k_initdet(const unsigned* __restrict__ p) {
    int stride = gridDim.x * blockDim.x;
    for (int t = blockIdx.x * blockDim.x + threadIdx.x; t < EE; t += stride) {
        g_small[OFF_A + t]  = 0.0f;
        g_small[OFF_T1 + t] = 0.0f;   // L scratch for symmetric accumulation
        g_cnt_he[t] = 0; g_cnt_col[t] = 0;
        g_cur_he[t] = 0; g_cur_col[t] = 0;
        if (t < NN) g_dnode[t] = 0;
    }
    if (blockIdx.x == 0) {
        __shared__ int nz;
        if (threadIdx.x == 0) nz = 0;
        __syncthreads();
        int any = 0;
        for (int i = threadIdx.x; i < 4096; i += blockDim.x)
            any |= (p[2 * i + 1] != 0u);
        if (any) atomicOr(&nz, 1);
        __syncthreads();
        if (threadIdx.x == 0) g_is64 = nz ? 0 : 1;
    }
}

// ---------------- fused histograms ----------------
__global__ void k_hist(const void* __restrict__ ei, const void* __restrict__ eei) {
    int is64 = g_is64;
    __shared__ int h[NN];
    if (blockIdx.x < 1024) {
        for (int i = threadIdx.x; i < NN; i += blockDim.x) h[i] = 0;
        __syncthreads();
        int stride = 1024 * blockDim.x;
        for (int i = blockIdx.x * blockDim.x + threadIdx.x; i < NNZ; i += stride) {
            int src = ldidx(ei, i, is64);
            int he  = ldidx(ei, (long long)NNZ + i, is64);
            atomicAdd(&g_cnt_he[he], 1);
            atomicAdd(&h[src], 1);
        }
        __syncthreads();
        for (int i = threadIdx.x; i < NN; i += blockDim.x)
            if (h[i]) atomicAdd(&g_dnode[i], h[i]);
    } else {
        int b = blockIdx.x - 1024;
        int stride = 1024 * blockDim.x;
        for (int j = b * blockDim.x + threadIdx.x; j < EENNZ; j += stride) {
            int col = ldidx(eei, (long long)EENNZ + j, is64);
            atomicAdd(&g_cnt_col[col], 1);
        }
    }
}

// ------- 64K-bin exclusive scan (2 blocks: one per CSR) + degree prep -------
__global__ void k_scan() {
    int which = blockIdx.x;
    const int* cnt = which ? g_cnt_col : g_cnt_he;
    int*       off = which ? g_off_col : g_off_he;
    __shared__ int s[1024];
    int t = threadIdx.x;
    int base = t * 64;
    int sum = 0;
#pragma unroll 8
    for (int i = 0; i < 64; i++) sum += cnt[base + i];
    s[t] = sum;
    __syncthreads();
    for (int o = 1; o < 1024; o <<= 1) {
        int v = (t >= o) ? s[t - o] : 0;
        __syncthreads();
        s[t] += v;
        __syncthreads();
    }
    int run = s[t] - sum;  // exclusive prefix
    for (int i = 0; i < 64; i++) { off[base + i] = run; run += cnt[base + i]; }
    if (t == 1023) off[EE] = run;
    if (which) {
        for (int i = t; i < EE; i += 1024)
            g_dis[i] = rsqrtf((float)(g_cnt_col[i] + 1));  // +1 self loop
    } else {
        if (t < NN) g_dinv[t] = g_dnode[t] > 0 ? 1.0f / (float)g_dnode[t] : 0.0f;
    }
}

// ------- fused scatters into CSR + diagonal of A (shared float histogram) ----
__global__ void k_scatter(const void* __restrict__ ei, const void* __restrict__ eei) {
    __shared__ float hd[NN];
    int is64 = g_is64;
    int stride = 1024 * blockDim.x;
    if (blockIdx.x < 1024) {
        for (int i = threadIdx.x; i < NN; i += blockDim.x) hd[i] = 0.0f;
        __syncthreads();
        for (int i = blockIdx.x * blockDim.x + threadIdx.x; i < NNZ; i += stride) {
            int src = ldidx(ei, i, is64);
            int he  = ldidx(ei, (long long)NNZ + i, is64);
            int pos = g_off_he[he] + atomicAdd(&g_cur_he[he], 1);
            g_members[pos] = src;
            atomicAdd(&hd[src], 1.0f / (float)g_cnt_he[he]);
        }
        __syncthreads();
        for (int i = threadIdx.x; i < NN; i += blockDim.x)
            if (hd[i] != 0.0f) atomicAdd(&g_small[OFF_A + i * 257], hd[i]);
    } else {
        int b = blockIdx.x - 1024;
        for (int j = b * blockDim.x + threadIdx.x; j < EENNZ; j += stride) {
            int row = ldidx(eei, j, is64);
            int col = ldidx(eei, (long long)EENNZ + j, is64);
            int pos = g_off_col[col] + atomicAdd(&g_cur_col[col], 1);
            g_rows[pos] = row;
        }
    }
}

// -------- upper-triangular (list-position) accumulation into L --------------
__global__ void k_accA() {
    int w    = (blockIdx.x * blockDim.x + threadIdx.x) >> 5;
    int lane = threadIdx.x & 31;
    if (w >= EE) return;
    int s = g_off_he[w], e = g_off_he[w + 1];
    int k = e - s;
    if (k <= 1) return;
    float binv = 1.0f / (float)k;
    float* L = &g_small[OFF_T1];
    int tot = k * k;
    for (int p = lane; p < tot; p += 32) {
        int i = p / k, j = p - i * k;
        if (j > i) {
            int mi = g_members[s + i], mj = g_members[s + j];
            atomicAdd(&L[mi * 256 + mj], binv);
        }
    }
}

// -------- A = L + L^T (off-diag), diag += 2*L_diag (dup members) -------------
__global__ void k_sym() {
    int i = blockIdx.x, j = threadIdx.x;
    float* A = &g_small[OFF_A];
    const float* L = &g_small[OFF_T1];
    if (j > i) {
        float sv = L[i * 256 + j] + L[j * 256 + i];
        A[i * 256 + j] = sv;
        A[j * 256 + i] = sv;
    } else if (j == i) {
        A[i * 257] += 2.0f * L[i * 257];
    }
}

// ---------------- small GEMM: 32x32 tile, 2x2 micro, 256 threads -------------
__global__ void k_gemm(const float* __restrict__ A, const float* __restrict__ B,
                       float* __restrict__ C, int Mm, int Nn, int Kk,
                       const float* __restrict__ bias,
                       const float* __restrict__ rowscale,
                       int act, int transA) {
    __shared__ float As[16][34];   // [k][m]
    __shared__ float Bs[16][34];   // [k][n]
    int tid = threadIdx.x;
    int tx = tid & 15, ty = tid >> 4;
    int row0 = blockIdx.y * 32 + ty * 2;
    int col0 = blockIdx.x * 32 + tx * 2;
    float acc00 = 0.f, acc01 = 0.f, acc10 = 0.f, acc11 = 0.f;
    for (int kt = 0; kt < Kk; kt += 16) {
        if (transA) {
            int m = tid & 31, c = tid >> 5;
            As[c][m]     = A[(kt + c) * Mm + blockIdx.y * 32 + m];
            As[c + 8][m] = A[(kt + c + 8) * Mm + blockIdx.y * 32 + m];
        } else {
            int c = tid & 15, m = tid >> 4;
            As[c][m]      = A[(blockIdx.y * 32 + m) * Kk + kt + c];
            As[c][m + 16] = A[(blockIdx.y * 32 + m + 16) * Kk + kt + c];
        }
        {
            int n = tid & 31, r = tid >> 5;
            Bs[r][n]     = B[(kt + r) * Nn + blockIdx.x * 32 + n];
            Bs[r + 8][n] = B[(kt + r + 8) * Nn + blockIdx.x * 32 + n];
        }
        __syncthreads();
#pragma unroll
        for (int kk = 0; kk < 16; kk++) {
            float2 a = *(const float2*)&As[kk][ty * 2];
            float2 b = *(const float2*)&Bs[kk][tx * 2];
            acc00 += a.x * b.x; acc01 += a.x * b.y;
            acc10 += a.y * b.x; acc11 += a.y * b.y;
        }
        __syncthreads();
    }
    float r0 = rowscale ? rowscale[row0]     : 1.0f;
    float r1 = rowscale ? rowscale[row0 + 1] : 1.0f;
    float b0 = bias ? bias[col0]     : 0.0f;
    float b1 = bias ? bias[col0 + 1] : 0.0f;
    float o00 = acc00 * r0 + b0, o01 = acc01 * r0 + b1;
    float o10 = acc10 * r1 + b0, o11 = acc11 * r1 + b1;
    if (act) { o00 = lrelu(o00); o01 = lrelu(o01); o10 = lrelu(o10); o11 = lrelu(o11); }
    C[row0 * Nn + col0]           = o00;
    C[row0 * Nn + col0 + 1]       = o01;
    C[(row0 + 1) * Nn + col0]     = o10;
    C[(row0 + 1) * Nn + col0 + 1] = o11;
}

// ---------------- fold biases ----------------
__global__ void k_smallvec(const float* __restrict__ bg, const float* __restrict__ Wl2,
                           const float* __restrict__ bl2, const float* __restrict__ bl3,
                           const float* __restrict__ Wo, const float* __restrict__ bo) {
    int j = threadIdx.x;
    float a = 0.0f;
    for (int k = 0; k < 256; k++) a += bg[k] * Wl2[k * 256 + j];
    g_b2[j] = a + bl2[j];
    if (j < 64) {
        float c = 0.0f;
        for (int k = 0; k < 128; k++) c += bl3[k] * Wo[k * 64 + j];
        g_bc[j] = c + bo[j];
    }
}

// ------ w[e] = dis[e] * mean_{members} T[src]  (MLP-8 gathers) ---------------
__global__ void k_u() {
    int e = blockIdx.x * 4 + (threadIdx.x >> 6);
    int t = threadIdx.x & 63;
    int s = g_off_he[e], en = g_off_he[e + 1];
    const float* __restrict__ T = &g_small[OFF_T];
    float4 acc = make_float4(0.f, 0.f, 0.f, 0.f);
    int m = s;
    for (; m + 8 <= en; m += 8) {
        int idx[8];
#pragma unroll
        for (int q = 0; q < 8; q++) idx[q] = g_members[m + q];
        float4 v[8];
#pragma unroll
        for (int q = 0; q < 8; q++) v[q] = *(const float4*)&T[idx[q] * 256 + t * 4];
#pragma unroll
        for (int q = 0; q < 8; q++) {
            acc.x += v[q].x; acc.y += v[q].y; acc.z += v[q].z; acc.w += v[q].w;
        }
    }
    for (; m < en; m++) {
        int src = g_members[m];
        float4 v = *(const float4*)&T[src * 256 + t * 4];
        acc.x += v.x; acc.y += v.y; acc.z += v.z; acc.w += v.w;
    }
    int k = en - s;
    float sc = (k > 0 ? 1.0f / (float)k : 0.0f) * g_dis[e];
    float4 o = make_float4(acc.x * sc, acc.y * sc, acc.z * sc, acc.w * sc);
    *(float4*)&g_w[(size_t)e * 256 + t * 4] = o;
}

// --- GCN agg (gather by col) + lin2 bias + leaky (MLP-8 gathers) -------------
__global__ void k_agg() {
    int c = blockIdx.x * 4 + (threadIdx.x >> 6);
    int t = threadIdx.x & 63;
    float4 acc = *(const float4*)&g_w[(size_t)c * 256 + t * 4];  // self loop
    int s = g_off_col[c], en = g_off_col[c + 1];
    int j = s;
    for (; j + 8 <= en; j += 8) {
        int idx[8];
#pragma unroll
        for (int q = 0; q < 8; q++) idx[q] = g_rows[j + q];
        float4 v[8];
#pragma unroll
        for (int q = 0; q < 8; q++) v[q] = *(const float4*)&g_w[(size_t)idx[q] * 256 + t * 4];
#pragma unroll
        for (int q = 0; q < 8; q++) {
            acc.x += v[q].x; acc.y += v[q].y; acc.z += v[q].z; acc.w += v[q].w;
        }
    }
    for (; j < en; j++) {
        int r = g_rows[j];
        float4 v = *(const float4*)&g_w[(size_t)r * 256 + t * 4];
        acc.x += v.x; acc.y += v.y; acc.z += v.z; acc.w += v.w;
    }
    float dc = g_dis[c];
    float4 b = *(const float4*)&g_b2[t * 4];
    float4 o;
    o.x = lrelu(dc * acc.x + b.x);
    o.y = lrelu(dc * acc.y + b.y);
    o.z = lrelu(dc * acc.z + b.z);
    o.w = lrelu(dc * acc.w + b.w);
    *(float4*)&g_v[(size_t)c * 256 + t * 4] = o;
}

// ---------------- motif min (3 members) fused with GEMM [32 motifs/block] ----
__global__ void k_motif(const void* __restrict__ mei, float* __restrict__ out) {
    __shared__ float sM[256 * 36];
    __shared__ int sIdx[96];
    int tid = threadIdx.x;           // 128 threads
    int is64 = g_is64;
    int mbase = blockIdx.x * 32;
    if (tid < 96)
        sIdx[tid] = ldidx(mei, 3LL * mbase + tid, is64);
    __syncthreads();
    for (int mm = 0; mm < 32; mm++) {
        const float* __restrict__ r0 = &g_v[(size_t)sIdx[3 * mm]     * 256];
        const float* __restrict__ r1 = &g_v[(size_t)sIdx[3 * mm + 1] * 256];
        const float* __restrict__ r2 = &g_v[(size_t)sIdx[3 * mm + 2] * 256];
        for (int c = tid; c < 256; c += 128) {
            float v = fminf(fminf(r0[c], r1[c]), r2[c]);
            sM[c * 36 + mm] = v;
        }
    }
    __syncthreads();
    int c0 = (tid & 15) * 4;
    int m0 = (tid >> 4) * 4;
    float acc[4][4];
#pragma unroll
    for (int a = 0; a < 4; a++)
#pragma unroll
        for (int b = 0; b < 4; b++) acc[a][b] = 0.0f;
#pragma unroll 4
    for (int k = 0; k < 256; k++) {
        float4 wv = *(const float4*)&g_Wc[k * 64 + c0];
        float4 mv = *(const float4*)&sM[k * 36 + m0];
        acc[0][0] += mv.x * wv.x; acc[0][1] += mv.x * wv.y; acc[0][2] += mv.x * wv.z; acc[0][3] += mv.x * wv.w;
        acc[1][0] += mv.y * wv.x; acc[1][1] += mv.y * wv.y; acc[1][2] += mv.y * wv.z; acc[1][3] += mv.y * wv.w;
        acc[2][0] += mv.z * wv.x; acc[2][1] += mv.z * wv.y; acc[2][2] += mv.z * wv.z; acc[2][3] += mv.z * wv.w;
        acc[3][0] += mv.w * wv.x; acc[3][1] += mv.w * wv.y; acc[3][2] += mv.w * wv.z; acc[3][3] += mv.w * wv.w;
    }
    float4 bc = *(const float4*)&g_bc[c0];
#pragma unroll
    for (int a = 0; a < 4; a++) {
        int t = mbase + m0 + a;
        float4 o = make_float4(acc[a][0] + bc.x, acc[a][1] + bc.y,
                               acc[a][2] + bc.z, acc[a][3] + bc.w);
        *(float4*)&out[(size_t)t * 64 + c0] = o;
    }
}

// ---------------- host ----------------
extern "C" void kernel_launch(void* const* d_in, const int* in_sizes, int n_in,
                              void* d_out, int out_size) {
    const float* node_embeds = (const float*)d_in[0];
    const float* W_hg   = (const float*)d_in[1];
    const float* b_hg   = (const float*)d_in[2];
    const float* W_lin  = (const float*)d_in[3];
    const float* b_lin  = (const float*)d_in[4];
    const float* W_gcn  = (const float*)d_in[5];
    const float* b_gcn  = (const float*)d_in[6];
    const float* W_lin2 = (const float*)d_in[7];
    const float* b_lin2 = (const float*)d_in[8];
    const float* W_lin3 = (const float*)d_in[9];
    const float* b_lin3 = (const float*)d_in[10];
    const float* W_out  = (const float*)d_in[11];
    const float* b_out  = (const float*)d_in[12];
    const void*  ei     = d_in[13];
    const void*  eei    = d_in[14];
    const void*  mei    = d_in[15];
    float* out = (float*)d_out;

    float* smallp = nullptr;
    float* Wcp    = nullptr;
    float* dinvp  = nullptr;
    cudaGetSymbolAddress((void**)&smallp, g_small);
    cudaGetSymbolAddress((void**)&Wcp,    g_Wc);
    cudaGetSymbolAddress((void**)&dinvp,  g_dinv);
    float* Ap  = smallp + OFF_A;
    float* xp  = smallp + OFF_X;
    float* yp  = smallp + OFF_Y;
    float* Gp  = smallp + OFF_G;
    float* y2p = smallp + OFF_Y2;
    float* T1p = smallp + OFF_T1;
    float* Tp  = smallp + OFF_T;

    k_initdet<<<256, 256>>>((const unsigned*)ei);
    k_hist<<<2048, 256>>>(ei, eei);
    k_scan<<<2, 1024>>>();
    k_scatter<<<2048, 256>>>(ei, eei);
    k_accA<<<8192, 256>>>();
    k_sym<<<256, 256>>>();

    // x = node_embeds @ W_hg
    k_gemm<<<dim3(8, 8), 256>>>(node_embeds, W_hg, xp, 256, 256, 256, nullptr, nullptr, 0, 0);
    // y = leaky( dinv * (A @ x) + b_hg )
    k_gemm<<<dim3(8, 8), 256>>>(Ap, xp, yp, 256, 256, 256, b_hg, dinvp, 1, 0);
    // G = y^T @ y
    k_gemm<<<dim3(8, 8), 256>>>(yp, yp, Gp, 256, 256, 256, nullptr, nullptr, 0, 1);
    // y2 = leaky( G @ W_lin + b_lin )
    k_gemm<<<dim3(8, 8), 256>>>(Gp, W_lin, y2p, 256, 256, 256, b_lin, nullptr, 1, 0);
    // T = y2 @ W_gcn @ W_lin2
    k_gemm<<<dim3(8, 8), 256>>>(y2p, W_gcn, T1p, 256, 256, 256, nullptr, nullptr, 0, 0);
    k_gemm<<<dim3(8, 8), 256>>>(T1p, W_lin2, Tp, 256, 256, 256, nullptr, nullptr, 0, 0);
    // Wc = W_lin3 @ W_out
    k_gemm<<<dim3(2, 8), 256>>>(W_lin3, W_out, Wcp, 256, 64, 128, nullptr, nullptr, 0, 0);
    k_smallvec<<<1, 256>>>(b_gcn, W_lin2, b_lin2, b_lin3, W_out, b_out);

    k_u<<<16384, 256>>>();
    k_agg<<<16384, 256>>>();
    k_motif<<<2048, 128>>>(mei, out);
}